// round 14
// baseline (speedup 1.0000x reference)
#include <cuda_runtime.h>
#include <cstdint>

// ---------------------------------------------------------------------------
// TransitionLayer: out[b,i,j] = softmax_j( log(clip(g,1e-6))/0.5 + mask ), j>=i
//   g = 1 - prod_r (1 - alpha*clause_r);  clause = prod_m (A + C*u[b,m])
//   A = s0+s2, C = s1-s2, s = softmax(sel/0.8); softmax(log g/0.5) == norm g^2
//
// UNIFORM work units. 55 pairs -> 10 units of 5-6:
//   unit 2k   (A): row k pairs j=k..k+5            (6 pairs)
//   unit 2k+1 (B): row k pairs j=k+6..9 (4-k) + all of row 9-k (k+1)  (5)
// Thread = (batch, unit): 160-thread blocks (16 batches), 1024 blocks,
// 5120 UNIFORM warps -> no slow-block tail (R10's limiter: single wave,
// kernel time = row-0 blocks). Row-k sum shared by units 2k/2k+1 via
// shfl_xor(1) (A always on even lane, B adjacent odd lane, same warp).
// ---------------------------------------------------------------------------

__device__ __constant__ int c_PAIR_I[55] = {
    0,0,0,0,0,0,0,0,0,0, 1,1,1,1,1,1,1,1,1, 2,2,2,2,2,2,2,2,
    3,3,3,3,3,3,3, 4,4,4,4,4,4, 5,5,5,5,5, 6,6,6,6, 7,7,7, 8,8, 9};
__device__ __constant__ int c_PAIR_J[55] = {
    0,1,2,3,4,5,6,7,8,9, 1,2,3,4,5,6,7,8,9, 2,3,4,5,6,7,8,9,
    3,4,5,6,7,8,9, 4,5,6,7,8,9, 5,6,7,8,9, 6,7,8,9, 7,8,9, 8,9, 9};
__device__ __constant__ int c_PBASE[10] = {0,10,19,27,34,40,45,49,52,54};

#define CSTRIDE 23   // float4 stride per pair (22 used + 1 pad -> bank spread)

__global__ __launch_bounds__(160, 7)
void tl_main(const float* __restrict__ pred,
             const float* __restrict__ sel,
             const float* __restrict__ alog,
             float* __restrict__ out) {
    __shared__ float4 s_coef[55 * CSTRIDE];   // [p*23 + m] = {A0,C0,A1,C1}
    __shared__ float  s_alpha[110];           // [p*2 + r]

    const int tid = threadIdx.x;

    // ---- stage ALL 55 pairs' coefficients (block covers every unit) ----
#pragma unroll 1
    for (int e = tid; e < 55 * 22; e += 160) {
        int p = e / 22;
        int m = e - p * 22;
        int i = c_PAIR_I[p], j = c_PAIR_J[p];
        float AC[4];
#pragma unroll
        for (int r = 0; r < 2; r++) {
            int base = (((i * 10 + j) * 2 + r) * 22 + m) * 3;
            float s0 = sel[base + 0] * 1.25f;
            float s1 = sel[base + 1] * 1.25f;
            float s2 = sel[base + 2] * 1.25f;
            float mx = fmaxf(s0, fmaxf(s1, s2));
            float e0 = expf(s0 - mx), e1 = expf(s1 - mx), e2 = expf(s2 - mx);
            float inv = 1.0f / (e0 + e1 + e2);
            AC[2 * r + 0] = (e0 + e2) * inv;
            AC[2 * r + 1] = (e1 - e2) * inv;
        }
        s_coef[p * CSTRIDE + m] = make_float4(AC[0], AC[1], AC[2], AC[3]);
    }
    if (tid < 110) {
        int p = tid >> 1, r = tid & 1;
        int i = c_PAIR_I[p], j = c_PAIR_J[p];
        float a = alog[(i * 10 + j) * 2 + r];
        s_alpha[tid] = 1.0f / (1.0f + expf(-a));
    }
    __syncthreads();

    // ---- unit decode ----
    const int bl  = tid / 10;          // local batch 0..15
    const int un  = tid - bl * 10;     // unit 0..9
    const int b   = blockIdx.x * 16 + bl;
    const int k   = un >> 1;           // rowset / primary row
    const int isB = un & 1;
    const int i   = k;
    const int si  = 9 - k;             // secondary row (B only)
    const int cnt0   = isB ? (4 - k) : 6;          // primary-row pairs
    const int start0 = c_PBASE[i] + (isB ? 6 : 0);
    const int cnt1   = isB ? (k + 1) : 0;          // secondary-row pairs
    const int start1 = isB ? c_PBASE[si] : 0;
    const int total  = cnt0 + cnt1;                // 6 (A) or 5 (B)

    // ---- load u (22 contiguous floats, 8B-aligned rows) ----
    float u[22];
    {
        const float2* __restrict__ pv =
            reinterpret_cast<const float2*>(pred + (size_t)b * 22);
#pragma unroll
        for (int t = 0; t < 11; t++) {
            float2 v = pv[t];
            u[2 * t + 0] = v.x;
            u[2 * t + 1] = v.y;
        }
    }

    // ---- clause products for up to 6 pairs (statically unrolled) ----
    float wa[6];
    float sum0 = 0.0f, sum1 = 0.0f;
#pragma unroll
    for (int idx = 0; idx < 6; idx++) {
        if (idx < total) {
            int p = (idx < cnt0) ? (start0 + idx) : (start1 + (idx - cnt0));
            const float4* cp = s_coef + p * CSTRIDE;
            float c0a = 1.0f, c0b = 1.0f, c1a = 1.0f, c1b = 1.0f;
#pragma unroll
            for (int m = 0; m < 22; m += 2) {
                float4 k0 = cp[m];
                float4 k1 = cp[m + 1];
                float l0a = fmaf(k0.y, u[m],     k0.x);
                float l1a = fmaf(k0.w, u[m],     k0.z);
                float l0b = fmaf(k1.y, u[m + 1], k1.x);
                float l1b = fmaf(k1.w, u[m + 1], k1.z);
                c0a *= l0a;  c1a *= l1a;
                c0b *= l0b;  c1b *= l1b;
            }
            float cl0 = c0a * c0b;
            float cl1 = c1a * c1b;
            float x = s_alpha[2 * p + 0] * cl0;
            float y = s_alpha[2 * p + 1] * cl1;
            float g = fmaf(y, 1.0f - x, x);
            g = fmaxf(g, 1e-6f);
            g = g * g;
            if (idx < cnt0) sum0 += g; else sum1 += g;
            wa[idx] = g;
        }
    }

    // ---- row-k sum: combine A/B halves (adjacent lanes) ----
    float other = __shfl_xor_sync(0xffffffffu, sum0, 1);
    float ti    = sum0 + other;
    float inv_i = 1.0f / ti;
    float inv_s = 1.0f / sum1;          // B only; unused (guarded) otherwise

    float* rowi = out + (size_t)b * 100 + i * 10;
    float* rows = out + (size_t)b * 100 + si * 10;

    // zeros: A writes j<i of row i; B writes j<si of row si
#pragma unroll
    for (int z = 0; z < 9; z++) {
        if (!isB) { if (z < i)  rowi[z] = 0.0f; }
        else      { if (z < si) rows[z] = 0.0f; }
    }
    // values
    const int posb = i + (isB ? 6 : 0);
#pragma unroll
    for (int idx = 0; idx < 6; idx++) {
        if (idx < cnt0) {
            rowi[posb + idx] = wa[idx] * inv_i;
        } else if (idx < total) {
            rows[si + (idx - cnt0)] = wa[idx] * inv_s;
        }
    }
}

extern "C" void kernel_launch(void* const* d_in, const int* in_sizes, int n_in,
                              void* d_out, int out_size) {
    const float* pred = (const float*)d_in[0];  // (16384, 22) f32
    const float* sel  = (const float*)d_in[1];  // (10,10,2,22,3) f32
    const float* alog = (const float*)d_in[2];  // (10,10,2) f32
    float* out = (float*)d_out;                 // (16384, 10, 10) f32

    tl_main<<<1024, 160>>>(pred, sel, alog, out);
}

// round 17
// speedup vs baseline: 1.2018x; 1.2018x over previous
#include <cuda_runtime.h>
#include <cstdint>

// ---------------------------------------------------------------------------
// TransitionLayer: out[b,i,j] = softmax_j( log(clip(g,1e-6))/0.5 + mask ), j>=i
//   g = 1 - prod_r (1 - alpha*clause_r);  clause = prod_m (A + C*u[b,m])
//   A = s0+s2, C = s1-s2, s = softmax(sel/0.8); softmax(log g/0.5) == norm g^2
//
// HALF-WARP units. Warp = 16 batches x {A,B} of rowset k:
//   lanes 0-15  (A): row k pairs j=k..k+5              (6 pairs)
//   lanes 16-31 (B): row k pairs j=k+6..9 + row 9-k    (5 pairs)
// -> only 2 distinct smem addresses per LDS (N=2) vs R14's ~10 (L1=63%
//    regression), work warp-uniform (no R10 tail), 5120 warps.
// Row-k sum combine: shfl_xor(16) within the warp.
// ---------------------------------------------------------------------------

__device__ __constant__ int c_PAIR_I[55] = {
    0,0,0,0,0,0,0,0,0,0, 1,1,1,1,1,1,1,1,1, 2,2,2,2,2,2,2,2,
    3,3,3,3,3,3,3, 4,4,4,4,4,4, 5,5,5,5,5, 6,6,6,6, 7,7,7, 8,8, 9};
__device__ __constant__ int c_PAIR_J[55] = {
    0,1,2,3,4,5,6,7,8,9, 1,2,3,4,5,6,7,8,9, 2,3,4,5,6,7,8,9,
    3,4,5,6,7,8,9, 4,5,6,7,8,9, 5,6,7,8,9, 6,7,8,9, 7,8,9, 8,9, 9};
__device__ __constant__ int c_PBASE[10] = {0,10,19,27,34,40,45,49,52,54};

__global__ __launch_bounds__(128, 8)
void tl_main(const float* __restrict__ pred,
             const float* __restrict__ sel,
             const float* __restrict__ alog,
             float* __restrict__ out) {
    __shared__ float4 s_coef[55 * 22];   // [p*22 + m] = {A0,C0,A1,C1}
    __shared__ float  s_alpha[110];      // [p*2 + r]

    const int tid = threadIdx.x;

    // ---- stage ALL 55 pairs' coefficients ----
#pragma unroll 1
    for (int e = tid; e < 55 * 22; e += 128) {
        int p = e / 22;
        int m = e - p * 22;
        int i = c_PAIR_I[p], j = c_PAIR_J[p];
        float AC[4];
#pragma unroll
        for (int r = 0; r < 2; r++) {
            int base = (((i * 10 + j) * 2 + r) * 22 + m) * 3;
            float s0 = sel[base + 0] * 1.25f;
            float s1 = sel[base + 1] * 1.25f;
            float s2 = sel[base + 2] * 1.25f;
            float mx = fmaxf(s0, fmaxf(s1, s2));
            float e0 = expf(s0 - mx), e1 = expf(s1 - mx), e2 = expf(s2 - mx);
            float inv = 1.0f / (e0 + e1 + e2);
            AC[2 * r + 0] = (e0 + e2) * inv;
            AC[2 * r + 1] = (e1 - e2) * inv;
        }
        s_coef[e] = make_float4(AC[0], AC[1], AC[2], AC[3]);
    }
    if (tid < 110) {
        int p = tid >> 1, r = tid & 1;
        int i = c_PAIR_I[p], j = c_PAIR_J[p];
        float a = alog[(i * 10 + j) * 2 + r];
        s_alpha[tid] = 1.0f / (1.0f + expf(-a));
    }
    __syncthreads();

    // ---- decode: warp = (rowset k, 16 batches); half-warp = unit A/B ----
    const int warp = tid >> 5;
    const int lane = tid & 31;
    const int gw   = blockIdx.x * 4 + warp;          // 0..5119
    const int k    = gw % 5;                         // rowset
    const int bg   = gw / 5;                         // batch group 0..1023
    const int half = lane >> 4;                      // 0 = A, 1 = B
    const int b    = bg * 16 + (lane & 15);          // batch

    const int i   = k;
    const int si  = 9 - k;
    const int cnt0   = half ? (4 - k) : 6;           // row-k pairs this unit
    const int start0 = c_PBASE[i] + (half ? 6 : 0);
    const int cnt1   = half ? (k + 1) : 0;           // row-(9-k) pairs (B only)
    const int start1 = half ? c_PBASE[si] : 0;
    const int total  = cnt0 + cnt1;                  // 6 (A) or 5 (B)

    // ---- load u (22 contiguous floats, 8B-aligned rows) ----
    float u[22];
    {
        const float2* __restrict__ pv =
            reinterpret_cast<const float2*>(pred + (size_t)b * 22);
#pragma unroll
        for (int t = 0; t < 11; t++) {
            float2 v = pv[t];
            u[2 * t + 0] = v.x;
            u[2 * t + 1] = v.y;
        }
    }

    // ---- clause products: up to 6 pairs, 2 smem addresses per warp ----
    float wa[6];
    float sum0 = 0.0f, sum1 = 0.0f;
#pragma unroll
    for (int idx = 0; idx < 6; idx++) {
        if (idx < total) {
            int p = (idx < cnt0) ? (start0 + idx) : (start1 + (idx - cnt0));
            const float4* cp = s_coef + p * 22;
            float c0a = 1.0f, c0b = 1.0f, c1a = 1.0f, c1b = 1.0f;
#pragma unroll
            for (int m = 0; m < 22; m += 2) {
                float4 k0 = cp[m];
                float4 k1 = cp[m + 1];
                float l0a = fmaf(k0.y, u[m],     k0.x);
                float l1a = fmaf(k0.w, u[m],     k0.z);
                float l0b = fmaf(k1.y, u[m + 1], k1.x);
                float l1b = fmaf(k1.w, u[m + 1], k1.z);
                c0a *= l0a;  c1a *= l1a;
                c0b *= l0b;  c1b *= l1b;
            }
            float cl0 = c0a * c0b;
            float cl1 = c1a * c1b;
            float x = s_alpha[2 * p + 0] * cl0;
            float y = s_alpha[2 * p + 1] * cl1;
            float g = fmaf(y, 1.0f - x, x);
            g = fmaxf(g, 1e-6f);
            g = g * g;                   // softmax(logit/0.5) == normalize(g^2)
            if (idx < cnt0) sum0 += g; else sum1 += g;
            wa[idx] = g;
        }
    }

    // ---- row-k sum: A half + B half, partner at lane ^ 16 ----
    float other = __shfl_xor_sync(0xffffffffu, sum0, 16);
    float inv_i = 1.0f / (sum0 + other);
    float inv_s = 1.0f / sum1;           // B only; never stored on A lanes

    float* rowi = out + (size_t)b * 100 + i * 10;
    float* rows = out + (size_t)b * 100 + si * 10;

    // zeros: A writes j<i of row i; B writes j<si of row si
#pragma unroll
    for (int z = 0; z < 9; z++) {
        if (!half) { if (z < i)  rowi[z] = 0.0f; }
        else       { if (z < si) rows[z] = 0.0f; }
    }
    // values
    const int posb = i + (half ? 6 : 0);
#pragma unroll
    for (int idx = 0; idx < 6; idx++) {
        if (idx < cnt0) {
            rowi[posb + idx] = wa[idx] * inv_i;
        } else if (idx < total) {
            rows[si + (idx - cnt0)] = wa[idx] * inv_s;
        }
    }
}

extern "C" void kernel_launch(void* const* d_in, const int* in_sizes, int n_in,
                              void* d_out, int out_size) {
    const float* pred = (const float*)d_in[0];  // (16384, 22) f32
    const float* sel  = (const float*)d_in[1];  // (10,10,2,22,3) f32
    const float* alog = (const float*)d_in[2];  // (10,10,2) f32
    float* out = (float*)d_out;                 // (16384, 10, 10) f32

    tl_main<<<1280, 128>>>(pred, sel, alog, out);
}